// round 10
// baseline (speedup 1.0000x reference)
#include <cuda_runtime.h>
#include <cuda_bf16.h>
#include <cstdint>
#include <math.h>

#define QN 16
#define IN 64
#define PB 128
#define JN 256
#define DN 768

#define NSLAB 12               // 768 / 64 bf16 per slab
#define A_STAGE 8192           // 64 rows x 128B
#define B_STAGE 32768          // 256 rows x 128B
#define STAGE_BYTES (A_STAGE + B_STAGE)   // 40960
#define DYN_SMEM (2 * STAGE_BYTES)        // 81920

// Scratch (device globals: no allocation)
__device__ __nv_bfloat16 g_qbf[QN * IN * DN];    // 1.5 MB normalized q, bf16
__device__ __nv_bfloat16 g_pbf[PB * JN * DN];    // 48 MB normalized p, bf16
__device__ float g_scores[QN * PB];
__device__ float g_mv[QN * PB];

// ---------------------------------------------------------------------------
// Helpers
// ---------------------------------------------------------------------------
static __device__ __forceinline__ uint32_t smem_u32(const void* p) {
    uint32_t a;
    asm("{ .reg .u64 t; cvta.to.shared.u64 t, %1; cvt.u32.u64 %0, t; }"
        : "=r"(a) : "l"(p));
    return a;
}

#define SWZ(o) ((o) ^ (((o) >> 3) & 0x70))

static __device__ __forceinline__ void cpasync16(uint32_t saddr, const void* g) {
    asm volatile("cp.async.cg.shared.global [%0], [%1], 16;" :: "r"(saddr), "l"(g) : "memory");
}

static __device__ __forceinline__ void mbar_init(uint32_t a, uint32_t cnt) {
    asm volatile("mbarrier.init.shared.b64 [%0], %1;" :: "r"(a), "r"(cnt) : "memory");
}

static __device__ __forceinline__ void mbar_wait(uint32_t a, uint32_t ph) {
    asm volatile(
        "{\n\t.reg .pred P;\n\t"
        "WL%=:\n\t"
        "mbarrier.try_wait.parity.shared.b64 P, [%0], %1;\n\t"
        "@!P bra WL%=;\n\t}"
        :: "r"(a), "r"(ph) : "memory");
}

static __device__ __forceinline__ void mbar_arrive(uint32_t a) {
    asm volatile("mbarrier.arrive.shared.b64 _, [%0];" :: "r"(a) : "memory");
}

// NOINC: this thread contributes ONE real arrival (counted in init count)
// when all its prior cp.asyncs complete. The default (non-noinc) form is
// self-balancing (inc-at-issue) and never flips the phase -> R9 hang.
static __device__ __forceinline__ void cpasync_mbar_arrive_noinc(uint32_t a) {
    asm volatile("cp.async.mbarrier.arrive.noinc.shared.b64 [%0];" :: "r"(a) : "memory");
}

static __device__ __forceinline__ void ldmx4(uint32_t* r, uint32_t addr) {
    asm volatile("ldmatrix.sync.aligned.m8n8.x4.shared.b16 {%0,%1,%2,%3}, [%4];"
                 : "=r"(r[0]), "=r"(r[1]), "=r"(r[2]), "=r"(r[3]) : "r"(addr));
}

static __device__ __forceinline__ void mma_bf16(float* c, const uint32_t* a,
                                                uint32_t b0, uint32_t b1) {
    asm volatile(
        "mma.sync.aligned.m16n8k16.row.col.f32.bf16.bf16.f32 "
        "{%0,%1,%2,%3}, {%4,%5,%6,%7}, {%8,%9}, {%0,%1,%2,%3};"
        : "+f"(c[0]), "+f"(c[1]), "+f"(c[2]), "+f"(c[3])
        : "r"(a[0]), "r"(a[1]), "r"(a[2]), "r"(a[3]), "r"(b0), "r"(b1));
}

// ---------------------------------------------------------------------------
// Normalize + convert to bf16 (q, p) AND fp32 scores, one fused launch.
// Blocks [0, QN*IN): q rows. [QN*IN, +PB*JN): p rows. Last PB blocks: scores.
// ---------------------------------------------------------------------------
static __device__ __forceinline__ void norm_convert_row(const float* __restrict__ xr,
                                                        __nv_bfloat162* __restrict__ yr) {
    int t = threadIdx.x;  // 192
    float4 v = ((const float4*)xr)[t];
    float ss = v.x * v.x + v.y * v.y + v.z * v.z + v.w * v.w;
#pragma unroll
    for (int o = 16; o; o >>= 1) ss += __shfl_xor_sync(0xffffffffu, ss, o);
    __shared__ float red[6];
    if ((t & 31) == 0) red[t >> 5] = ss;
    __syncthreads();
    float tot = 0.f;
#pragma unroll
    for (int i = 0; i < 6; i++) tot += red[i];
    float inv = 1.0f / fmaxf(sqrtf(tot), 1e-12f);
    yr[2 * t + 0] = __floats2bfloat162_rn(v.x * inv, v.y * inv);
    yr[2 * t + 1] = __floats2bfloat162_rn(v.z * inv, v.w * inv);
}

__global__ void norm_all_kernel(const float* __restrict__ qh,
                                const float* __restrict__ ph) {
    size_t b = blockIdx.x;
    if (b < QN * IN) {
        norm_convert_row(qh + b * DN, (__nv_bfloat162*)(g_qbf + b * DN));
    } else if (b < (size_t)(QN * IN + PB * JN)) {
        size_t row = b - QN * IN;
        norm_convert_row(ph + row * DN, (__nv_bfloat162*)(g_pbf + row * DN));
    } else {
        // scores: this block handles page p, 16 q dots of 768 (fp32)
        int p = (int)(b - QN * IN - PB * JN);
        int wid = threadIdx.x >> 5, lane = threadIdx.x & 31;
        const float* pr = ph + (size_t)p * JN * DN;
        for (int q = wid; q < QN; q += 6) {
            const float* qr = qh + (size_t)q * IN * DN;
            float s = 0.f;
#pragma unroll
            for (int i = 0; i < DN / 32; i++)
                s = fmaf(qr[lane + 32 * i], pr[lane + 32 * i], s);
#pragma unroll
            for (int o = 16; o; o >>= 1) s += __shfl_xor_sync(0xffffffffu, s, o);
            if (lane == 0) g_scores[q * PB + p] = s;
        }
    }
}

// ---------------------------------------------------------------------------
// mv GEMM via bf16 mma.sync m16n8k16 on pre-normalized bf16 data.
// Grid (p=128, q=16). CTA tile 64(i) x 256(j), K=768 in 12 slabs of 64.
// 8 warps = 2(m) x 4(n); warp tile 32x64 = 2(mt) x 8(nt) fragments.
// 2-stage ring with mbarrier producer/consumer handoff (no CTA barriers in
// the mainloop): full[b] count=256 via cp.async.mbarrier.arrive.noinc,
// empty[b] count=8 (one arrive per warp). 2 CTAs/SM.
// ---------------------------------------------------------------------------
static __device__ __forceinline__ void load_slab(uint32_t stage_base, int mb, int p,
                                                 int k0, int tid) {
    // A: 64 rows x 64 bf16 (128B) = 512 x 16B chunks, 2 per thread
#pragma unroll
    for (int i = 0; i < 2; i++) {
        int idx = tid + 256 * i;
        int r = idx >> 3, c = idx & 7;
        const __nv_bfloat16* g = g_qbf + (size_t)(mb * 64 + r) * DN + k0 + c * 8;
        cpasync16(stage_base + SWZ(r * 128 + c * 16), g);
    }
    // B: 256 rows x 64 bf16 = 2048 x 16B, 8 per thread
    uint32_t bbase = stage_base + A_STAGE;
#pragma unroll
    for (int i = 0; i < 8; i++) {
        int idx = tid + 256 * i;
        int r = idx >> 3, c = idx & 7;
        const __nv_bfloat16* g = g_pbf + (size_t)(p * 256 + r) * DN + k0 + c * 8;
        cpasync16(bbase + SWZ(r * 128 + c * 16), g);
    }
}

__global__ __launch_bounds__(256, 2) void mv_tc_kernel() {
    extern __shared__ __align__(128) char dynraw[];
    __shared__ __align__(8) unsigned long long s_full[2], s_empty[2];
    __shared__ float s_wmax[8];

    const int tid = threadIdx.x;
    const int p = blockIdx.x;
    const int mb = blockIdx.y;  // q row (64 i's per q)
    const int w = tid >> 5, lane = tid & 31;
    const int wm = w >> 2, wn = w & 3;

    const uint32_t dynbase = smem_u32(dynraw);
    uint32_t fullb[2], emptyb[2];
#pragma unroll
    for (int i = 0; i < 2; i++) {
        fullb[i] = smem_u32(&s_full[i]);
        emptyb[i] = smem_u32(&s_empty[i]);
    }

    if (tid == 0) {
#pragma unroll
        for (int i = 0; i < 2; i++) {
            mbar_init(fullb[i], 256);
            mbar_init(emptyb[i], 8);
        }
    }
    __syncthreads();

    // A frag ldmatrix lane mapping (m16n8k16 x4)
    const int selA = lane >> 3;
    const int arow_l = (lane & 7) + ((selA & 1) << 3);
    const int achunk_h = selA >> 1;
    const int arx = lane & 7;
    uint32_t aRowOff[2];
#pragma unroll
    for (int mt = 0; mt < 2; mt++)
        aRowOff[mt] = (uint32_t)(wm * 32 + mt * 16 + arow_l) * 128u;

    // B frag mapping (x4 = two n8 tiles)
    const int jrow_l = (lane & 7) + ((lane >> 4) << 3);
    const int bchunk_h = (lane >> 3) & 1;
    const int brx = lane & 7;
    const uint32_t bRowOff0 = (uint32_t)(wn * 64 + jrow_l) * 128u;  // + np*16*128

    float acc[2][8][4];
#pragma unroll
    for (int mt = 0; mt < 2; mt++)
#pragma unroll
        for (int nt = 0; nt < 8; nt++)
#pragma unroll
            for (int c = 0; c < 4; c++) acc[mt][nt][c] = 0.f;

    // Prologue: fill both stages; completion tracked by full[] mbarriers
    load_slab(dynbase + 0 * STAGE_BYTES, mb, p, 0, tid);
    cpasync_mbar_arrive_noinc(fullb[0]);
    load_slab(dynbase + 1 * STAGE_BYTES, mb, p, 64, tid);
    cpasync_mbar_arrive_noinc(fullb[1]);

    int phF0 = 0, phF1 = 0, phE0 = 0, phE1 = 0;

    for (int s = 0; s < NSLAB; s++) {
        const int buf = s & 1;
        if (buf == 0) { mbar_wait(fullb[0], (uint32_t)phF0); phF0 ^= 1; }
        else          { mbar_wait(fullb[1], (uint32_t)phF1); phF1 ^= 1; }

        const uint32_t Ab = dynbase + buf * STAGE_BYTES;
        const uint32_t Bb = Ab + A_STAGE;

#pragma unroll
        for (int kk = 0; kk < 4; kk++) {
            const int ca = ((kk * 2 + achunk_h) ^ arx) << 4;
            const int cb = ((kk * 2 + bchunk_h) ^ brx) << 4;
            uint32_t a[2][4];
            ldmx4(a[0], Ab + aRowOff[0] + ca);
            ldmx4(a[1], Ab + aRowOff[1] + ca);
#pragma unroll
            for (int np = 0; np < 4; np++) {
                uint32_t b[4];
                ldmx4(b, Bb + bRowOff0 + (uint32_t)np * 2048u + cb);
                mma_bf16(acc[0][np * 2 + 0], a[0], b[0], b[1]);
                mma_bf16(acc[1][np * 2 + 0], a[1], b[0], b[1]);
                mma_bf16(acc[0][np * 2 + 1], a[0], b[2], b[3]);
                mma_bf16(acc[1][np * 2 + 1], a[1], b[2], b[3]);
            }
        }

        // this warp is done reading stage buf
        if (lane == 0) mbar_arrive(buf == 0 ? emptyb[0] : emptyb[1]);

        if (s + 2 < NSLAB) {
            // wait until ALL warps finished reading buf, then refill it
            if (buf == 0) { mbar_wait(emptyb[0], (uint32_t)phE0); phE0 ^= 1; }
            else          { mbar_wait(emptyb[1], (uint32_t)phE1); phE1 ^= 1; }
            load_slab(dynbase + buf * STAGE_BYTES, mb, p, (s + 2) * 64, tid);
            cpasync_mbar_arrive_noinc(buf == 0 ? fullb[0] : fullb[1]);
        }
    }

    // Epilogue: pure max (operands pre-normalized)
    float mx = -INFINITY;
#pragma unroll
    for (int mt = 0; mt < 2; mt++)
#pragma unroll
        for (int nt = 0; nt < 8; nt++)
#pragma unroll
            for (int c = 0; c < 4; c++) mx = fmaxf(mx, acc[mt][nt][c]);
#pragma unroll
    for (int o = 16; o; o >>= 1) mx = fmaxf(mx, __shfl_xor_sync(0xffffffffu, mx, o));
    if (lane == 0) s_wmax[w] = mx;
    __syncthreads();
    if (tid == 0) {
        float m = s_wmax[0];
#pragma unroll
        for (int i = 1; i < 8; i++) m = fmaxf(m, s_wmax[i]);
        g_mv[mb * PB + p] = m;
    }
}

// ---------------------------------------------------------------------------
// Final loss (unchanged logic)
// ---------------------------------------------------------------------------
__global__ void loss_kernel(float* __restrict__ out) {
    int tid = threadIdx.x;  // 512
    int w = tid >> 5;
    int lane = tid & 31;
    const float* sr = g_scores + w * PB;
    const float* mr = g_mv + w * PB;
    float s[4], m[4], si[4];
#pragma unroll
    for (int c = 0; c < 4; c++) {
        int j = lane + 32 * c;
        s[c] = sr[j];
        m[c] = mr[j];
        si[c] = s[c] + 0.3f * m[c];
    }
    float mxs = -INFINITY, mxm = -INFINITY, mxi = -INFINITY;
#pragma unroll
    for (int c = 0; c < 4; c++) {
        mxs = fmaxf(mxs, s[c]);
        mxm = fmaxf(mxm, m[c]);
        mxi = fmaxf(mxi, si[c]);
    }
#pragma unroll
    for (int o = 16; o; o >>= 1) {
        mxs = fmaxf(mxs, __shfl_xor_sync(0xffffffffu, mxs, o));
        mxm = fmaxf(mxm, __shfl_xor_sync(0xffffffffu, mxm, o));
        mxi = fmaxf(mxi, __shfl_xor_sync(0xffffffffu, mxi, o));
    }
    float es = 0.f, em = 0.f, ei = 0.f;
#pragma unroll
    for (int c = 0; c < 4; c++) {
        es += expf(s[c] - mxs);
        em += expf(m[c] - mxm);
        ei += expf(si[c] - mxi);
    }
#pragma unroll
    for (int o = 16; o; o >>= 1) {
        es += __shfl_xor_sync(0xffffffffu, es, o);
        em += __shfl_xor_sync(0xffffffffu, em, o);
        ei += __shfl_xor_sync(0xffffffffu, ei, o);
    }
    float lse_s = mxs + logf(es);
    float lse_m = mxm + logf(em);
    float lse_i = mxi + logf(ei);

    float k1 = 0.f, k2 = 0.f;
#pragma unroll
    for (int c = 0; c < 4; c++) {
        float t = si[c] - lse_i;
        float pb = expf(t);
        k1 += pb * (t - (s[c] - lse_s));
        k2 += pb * (t - (m[c] - lse_m));
    }
#pragma unroll
    for (int o = 16; o; o >>= 1) {
        k1 += __shfl_xor_sync(0xffffffffu, k1, o);
        k2 += __shfl_xor_sync(0xffffffffu, k2, o);
    }

    __shared__ float sm[16][4];
    if (lane == 0) {
        int tgt = w * 8;
        sm[w][0] = lse_s - sr[tgt];
        sm[w][1] = lse_i - (sr[tgt] + 0.3f * mr[tgt]);
        sm[w][2] = k1;
        sm[w][3] = k2;
    }
    __syncthreads();
    if (tid == 0) {
        float ce_s = 0.f, ce_i = 0.f, k1s = 0.f, k2s = 0.f;
#pragma unroll
        for (int i = 0; i < 16; i++) {
            ce_s += sm[i][0];
            ce_i += sm[i][1];
            k1s += sm[i][2];
            k2s += sm[i][3];
        }
        ce_s *= (1.0f / 16.0f);
        ce_i *= (1.0f / 16.0f);
        k1s *= (1.0f / 16.0f);
        k2s *= (1.0f / 16.0f);
        float L1 = 0.3f * (ce_s + k2s + ce_i);
        float L2 = 0.2f * (k1s + k2s);
        out[0] = 0.5f * (L1 + L2);
    }
}

// ---------------------------------------------------------------------------
extern "C" void kernel_launch(void* const* d_in, const int* in_sizes, int n_in,
                              void* d_out, int out_size) {
    const float* qh = (const float*)d_in[0];
    const float* ph = (const float*)d_in[1];
    if (n_in >= 2 && in_sizes[0] > in_sizes[1]) {
        const float* t = qh; qh = ph; ph = t;
    }

    cudaFuncSetAttribute(mv_tc_kernel, cudaFuncAttributeMaxDynamicSharedMemorySize,
                         DYN_SMEM);

    norm_all_kernel<<<QN * IN + PB * JN + PB, 192>>>(qh, ph);
    mv_tc_kernel<<<dim3(PB, QN), 256, DYN_SMEM>>>();
    loss_kernel<<<1, 512>>>((float*)d_out);
}

// round 11
// speedup vs baseline: 1.1506x; 1.1506x over previous
#include <cuda_runtime.h>
#include <cuda_bf16.h>
#include <cstdint>
#include <math.h>

#define QN 16
#define IN 64
#define PB 128
#define JN 256
#define DN 768

#define NSLAB 12               // 768 / 64 bf16 per slab
#define A_STAGE 8192           // 64 rows x 128B
#define B_STAGE 32768          // 256 rows x 128B
#define STAGE_BYTES (A_STAGE + B_STAGE)   // 40960
#define DYN_SMEM (2 * STAGE_BYTES)        // 81920

// Scratch (device globals: no allocation)
__device__ __nv_bfloat16 g_qbf[QN * IN * DN];    // 1.5 MB normalized q, bf16
__device__ __nv_bfloat16 g_pbf[PB * JN * DN];    // 48 MB normalized p, bf16
__device__ float g_scores[QN * PB];
__device__ float g_mv[QN * PB];

// ---------------------------------------------------------------------------
// Helpers
// ---------------------------------------------------------------------------
static __device__ __forceinline__ uint32_t smem_u32(const void* p) {
    uint32_t a;
    asm("{ .reg .u64 t; cvta.to.shared.u64 t, %1; cvt.u32.u64 %0, t; }"
        : "=r"(a) : "l"(p));
    return a;
}

#define SWZ(o) ((o) ^ (((o) >> 3) & 0x70))

static __device__ __forceinline__ void cpasync16(uint32_t saddr, const void* g) {
    asm volatile("cp.async.cg.shared.global [%0], [%1], 16;" :: "r"(saddr), "l"(g) : "memory");
}

static __device__ __forceinline__ void mbar_init(uint32_t a, uint32_t cnt) {
    asm volatile("mbarrier.init.shared.b64 [%0], %1;" :: "r"(a), "r"(cnt) : "memory");
}

static __device__ __forceinline__ void mbar_wait(uint32_t a, uint32_t ph) {
    asm volatile(
        "{\n\t.reg .pred P;\n\t"
        "WL%=:\n\t"
        "mbarrier.try_wait.parity.shared.b64 P, [%0], %1;\n\t"
        "@!P bra WL%=;\n\t}"
        :: "r"(a), "r"(ph) : "memory");
}

static __device__ __forceinline__ void mbar_arrive(uint32_t a) {
    asm volatile("mbarrier.arrive.shared.b64 _, [%0];" :: "r"(a) : "memory");
}

// NOINC: one real arrival (counted in init count) when this thread's prior
// cp.asyncs complete. (Non-noinc form is self-balancing -> R9 hang.)
static __device__ __forceinline__ void cpasync_mbar_arrive_noinc(uint32_t a) {
    asm volatile("cp.async.mbarrier.arrive.noinc.shared.b64 [%0];" :: "r"(a) : "memory");
}

static __device__ __forceinline__ void ldmx4(uint32_t* r, uint32_t addr) {
    asm volatile("ldmatrix.sync.aligned.m8n8.x4.shared.b16 {%0,%1,%2,%3}, [%4];"
                 : "=r"(r[0]), "=r"(r[1]), "=r"(r[2]), "=r"(r[3]) : "r"(addr));
}

static __device__ __forceinline__ void mma_bf16(float* c, const uint32_t* a,
                                                uint32_t b0, uint32_t b1) {
    asm volatile(
        "mma.sync.aligned.m16n8k16.row.col.f32.bf16.bf16.f32 "
        "{%0,%1,%2,%3}, {%4,%5,%6,%7}, {%8,%9}, {%0,%1,%2,%3};"
        : "+f"(c[0]), "+f"(c[1]), "+f"(c[2]), "+f"(c[3])
        : "r"(a[0]), "r"(a[1]), "r"(a[2]), "r"(a[3]), "r"(b0), "r"(b1));
}

// ---------------------------------------------------------------------------
// Normalize + convert to bf16: WARP per row (no smem, no __syncthreads).
// 8 warps/block; rows = QN*IN + PB*JN = 33792 = 4224 blocks exactly.
// Lane owns 6 float4 (24 floats) -> 12 bf16x2 stores (8B/lane contiguous).
// ---------------------------------------------------------------------------
__global__ __launch_bounds__(256) void norm_warp_kernel(const float* __restrict__ qh,
                                                        const float* __restrict__ ph) {
    const int lane = threadIdx.x & 31;
    const size_t row = (size_t)blockIdx.x * 8 + (threadIdx.x >> 5);

    const float* xr;
    __nv_bfloat162* yr;
    if (row < (size_t)(QN * IN)) {
        xr = qh + row * DN;
        yr = (__nv_bfloat162*)(g_qbf + row * DN);
    } else {
        size_t r = row - QN * IN;
        xr = ph + r * DN;
        yr = (__nv_bfloat162*)(g_pbf + r * DN);
    }

    float4 v[6];
    float ss = 0.f;
#pragma unroll
    for (int c = 0; c < 6; c++) {
        v[c] = ((const float4*)xr)[lane + 32 * c];
        ss += v[c].x * v[c].x + v[c].y * v[c].y + v[c].z * v[c].z + v[c].w * v[c].w;
    }
#pragma unroll
    for (int o = 16; o; o >>= 1) ss += __shfl_xor_sync(0xffffffffu, ss, o);
    const float inv = 1.0f / fmaxf(sqrtf(ss), 1e-12f);

#pragma unroll
    for (int c = 0; c < 6; c++) {
        int idx = lane + 32 * c;           // float4 index -> bf16x2 indices 2idx, 2idx+1
        yr[2 * idx + 0] = __floats2bfloat162_rn(v[c].x * inv, v[c].y * inv);
        yr[2 * idx + 1] = __floats2bfloat162_rn(v[c].z * inv, v[c].w * inv);
    }
}

// ---------------------------------------------------------------------------
// scores[q][p] = dot(q_hidden[q,0,:], p_hidden[p,0,:])  fp32, warp per pair
// ---------------------------------------------------------------------------
__global__ void scores_kernel(const float* __restrict__ qh,
                              const float* __restrict__ ph) {
    int p = blockIdx.x;
    int q = threadIdx.x >> 5;
    int lane = threadIdx.x & 31;
    const float* qr = qh + (size_t)q * IN * DN;
    const float* pr = ph + (size_t)p * JN * DN;
    float s = 0.f;
#pragma unroll
    for (int i = 0; i < DN / 32; i++) s = fmaf(qr[lane + 32 * i], pr[lane + 32 * i], s);
#pragma unroll
    for (int o = 16; o; o >>= 1) s += __shfl_xor_sync(0xffffffffu, s, o);
    if (lane == 0) g_scores[q * PB + p] = s;
}

// ---------------------------------------------------------------------------
// mv GEMM via bf16 mma.sync m16n8k16 on pre-normalized bf16 data.
// (verbatim R10 mbarrier-ring version: best measured mv ~119us)
// Grid (p=128, q=16). CTA tile 64(i) x 256(j), K=768 in 12 slabs of 64.
// 8 warps = 2(m) x 4(n); warp tile 32x64 = 2(mt) x 8(nt) fragments.
// 2-stage ring, full[b] count=256 (cp.async noinc arrivals),
// empty[b] count=8 (one arrive per warp). 2 CTAs/SM.
// ---------------------------------------------------------------------------
static __device__ __forceinline__ void load_slab(uint32_t stage_base, int mb, int p,
                                                 int k0, int tid) {
    // A: 64 rows x 64 bf16 (128B) = 512 x 16B chunks, 2 per thread
#pragma unroll
    for (int i = 0; i < 2; i++) {
        int idx = tid + 256 * i;
        int r = idx >> 3, c = idx & 7;
        const __nv_bfloat16* g = g_qbf + (size_t)(mb * 64 + r) * DN + k0 + c * 8;
        cpasync16(stage_base + SWZ(r * 128 + c * 16), g);
    }
    // B: 256 rows x 64 bf16 = 2048 x 16B, 8 per thread
    uint32_t bbase = stage_base + A_STAGE;
#pragma unroll
    for (int i = 0; i < 8; i++) {
        int idx = tid + 256 * i;
        int r = idx >> 3, c = idx & 7;
        const __nv_bfloat16* g = g_pbf + (size_t)(p * 256 + r) * DN + k0 + c * 8;
        cpasync16(bbase + SWZ(r * 128 + c * 16), g);
    }
}

__global__ __launch_bounds__(256, 2) void mv_tc_kernel() {
    extern __shared__ __align__(128) char dynraw[];
    __shared__ __align__(8) unsigned long long s_full[2], s_empty[2];
    __shared__ float s_wmax[8];

    const int tid = threadIdx.x;
    const int p = blockIdx.x;
    const int mb = blockIdx.y;  // q row (64 i's per q)
    const int w = tid >> 5, lane = tid & 31;
    const int wm = w >> 2, wn = w & 3;

    const uint32_t dynbase = smem_u32(dynraw);
    uint32_t fullb[2], emptyb[2];
#pragma unroll
    for (int i = 0; i < 2; i++) {
        fullb[i] = smem_u32(&s_full[i]);
        emptyb[i] = smem_u32(&s_empty[i]);
    }

    if (tid == 0) {
#pragma unroll
        for (int i = 0; i < 2; i++) {
            mbar_init(fullb[i], 256);
            mbar_init(emptyb[i], 8);
        }
    }
    __syncthreads();

    // A frag ldmatrix lane mapping (m16n8k16 x4)
    const int selA = lane >> 3;
    const int arow_l = (lane & 7) + ((selA & 1) << 3);
    const int achunk_h = selA >> 1;
    const int arx = lane & 7;
    uint32_t aRowOff[2];
#pragma unroll
    for (int mt = 0; mt < 2; mt++)
        aRowOff[mt] = (uint32_t)(wm * 32 + mt * 16 + arow_l) * 128u;

    // B frag mapping (x4 = two n8 tiles)
    const int jrow_l = (lane & 7) + ((lane >> 4) << 3);
    const int bchunk_h = (lane >> 3) & 1;
    const int brx = lane & 7;
    const uint32_t bRowOff0 = (uint32_t)(wn * 64 + jrow_l) * 128u;  // + np*16*128

    float acc[2][8][4];
#pragma unroll
    for (int mt = 0; mt < 2; mt++)
#pragma unroll
        for (int nt = 0; nt < 8; nt++)
#pragma unroll
            for (int c = 0; c < 4; c++) acc[mt][nt][c] = 0.f;

    // Prologue: fill both stages; completion tracked by full[] mbarriers
    load_slab(dynbase + 0 * STAGE_BYTES, mb, p, 0, tid);
    cpasync_mbar_arrive_noinc(fullb[0]);
    load_slab(dynbase + 1 * STAGE_BYTES, mb, p, 64, tid);
    cpasync_mbar_arrive_noinc(fullb[1]);

    int phF0 = 0, phF1 = 0, phE0 = 0, phE1 = 0;

    for (int s = 0; s < NSLAB; s++) {
        const int buf = s & 1;
        if (buf == 0) { mbar_wait(fullb[0], (uint32_t)phF0); phF0 ^= 1; }
        else          { mbar_wait(fullb[1], (uint32_t)phF1); phF1 ^= 1; }

        const uint32_t Ab = dynbase + buf * STAGE_BYTES;
        const uint32_t Bb = Ab + A_STAGE;

#pragma unroll
        for (int kk = 0; kk < 4; kk++) {
            const int ca = ((kk * 2 + achunk_h) ^ arx) << 4;
            const int cb = ((kk * 2 + bchunk_h) ^ brx) << 4;
            uint32_t a[2][4];
            ldmx4(a[0], Ab + aRowOff[0] + ca);
            ldmx4(a[1], Ab + aRowOff[1] + ca);
#pragma unroll
            for (int np = 0; np < 4; np++) {
                uint32_t b[4];
                ldmx4(b, Bb + bRowOff0 + (uint32_t)np * 2048u + cb);
                mma_bf16(acc[0][np * 2 + 0], a[0], b[0], b[1]);
                mma_bf16(acc[1][np * 2 + 0], a[1], b[0], b[1]);
                mma_bf16(acc[0][np * 2 + 1], a[0], b[2], b[3]);
                mma_bf16(acc[1][np * 2 + 1], a[1], b[2], b[3]);
            }
        }

        // this warp is done reading stage buf
        if (lane == 0) mbar_arrive(buf == 0 ? emptyb[0] : emptyb[1]);

        if (s + 2 < NSLAB) {
            // wait until ALL warps finished reading buf, then refill it
            if (buf == 0) { mbar_wait(emptyb[0], (uint32_t)phE0); phE0 ^= 1; }
            else          { mbar_wait(emptyb[1], (uint32_t)phE1); phE1 ^= 1; }
            load_slab(dynbase + buf * STAGE_BYTES, mb, p, (s + 2) * 64, tid);
            cpasync_mbar_arrive_noinc(buf == 0 ? fullb[0] : fullb[1]);
        }
    }

    // Epilogue: pure max (operands pre-normalized)
    float mx = -INFINITY;
#pragma unroll
    for (int mt = 0; mt < 2; mt++)
#pragma unroll
        for (int nt = 0; nt < 8; nt++)
#pragma unroll
            for (int c = 0; c < 4; c++) mx = fmaxf(mx, acc[mt][nt][c]);
#pragma unroll
    for (int o = 16; o; o >>= 1) mx = fmaxf(mx, __shfl_xor_sync(0xffffffffu, mx, o));
    if (lane == 0) s_wmax[w] = mx;
    __syncthreads();
    if (tid == 0) {
        float m = s_wmax[0];
#pragma unroll
        for (int i = 1; i < 8; i++) m = fmaxf(m, s_wmax[i]);
        g_mv[mb * PB + p] = m;
    }
}

// ---------------------------------------------------------------------------
// Final loss (unchanged logic)
// ---------------------------------------------------------------------------
__global__ void loss_kernel(float* __restrict__ out) {
    int tid = threadIdx.x;  // 512
    int w = tid >> 5;
    int lane = tid & 31;
    const float* sr = g_scores + w * PB;
    const float* mr = g_mv + w * PB;
    float s[4], m[4], si[4];
#pragma unroll
    for (int c = 0; c < 4; c++) {
        int j = lane + 32 * c;
        s[c] = sr[j];
        m[c] = mr[j];
        si[c] = s[c] + 0.3f * m[c];
    }
    float mxs = -INFINITY, mxm = -INFINITY, mxi = -INFINITY;
#pragma unroll
    for (int c = 0; c < 4; c++) {
        mxs = fmaxf(mxs, s[c]);
        mxm = fmaxf(mxm, m[c]);
        mxi = fmaxf(mxi, si[c]);
    }
#pragma unroll
    for (int o = 16; o; o >>= 1) {
        mxs = fmaxf(mxs, __shfl_xor_sync(0xffffffffu, mxs, o));
        mxm = fmaxf(mxm, __shfl_xor_sync(0xffffffffu, mxm, o));
        mxi = fmaxf(mxi, __shfl_xor_sync(0xffffffffu, mxi, o));
    }
    float es = 0.f, em = 0.f, ei = 0.f;
#pragma unroll
    for (int c = 0; c < 4; c++) {
        es += expf(s[c] - mxs);
        em += expf(m[c] - mxm);
        ei += expf(si[c] - mxi);
    }
#pragma unroll
    for (int o = 16; o; o >>= 1) {
        es += __shfl_xor_sync(0xffffffffu, es, o);
        em += __shfl_xor_sync(0xffffffffu, em, o);
        ei += __shfl_xor_sync(0xffffffffu, ei, o);
    }
    float lse_s = mxs + logf(es);
    float lse_m = mxm + logf(em);
    float lse_i = mxi + logf(ei);

    float k1 = 0.f, k2 = 0.f;
#pragma unroll
    for (int c = 0; c < 4; c++) {
        float t = si[c] - lse_i;
        float pb = expf(t);
        k1 += pb * (t - (s[c] - lse_s));
        k2 += pb * (t - (m[c] - lse_m));
    }
#pragma unroll
    for (int o = 16; o; o >>= 1) {
        k1 += __shfl_xor_sync(0xffffffffu, k1, o);
        k2 += __shfl_xor_sync(0xffffffffu, k2, o);
    }

    __shared__ float sm[16][4];
    if (lane == 0) {
        int tgt = w * 8;
        sm[w][0] = lse_s - sr[tgt];
        sm[w][1] = lse_i - (sr[tgt] + 0.3f * mr[tgt]);
        sm[w][2] = k1;
        sm[w][3] = k2;
    }
    __syncthreads();
    if (tid == 0) {
        float ce_s = 0.f, ce_i = 0.f, k1s = 0.f, k2s = 0.f;
#pragma unroll
        for (int i = 0; i < 16; i++) {
            ce_s += sm[i][0];
            ce_i += sm[i][1];
            k1s += sm[i][2];
            k2s += sm[i][3];
        }
        ce_s *= (1.0f / 16.0f);
        ce_i *= (1.0f / 16.0f);
        k1s *= (1.0f / 16.0f);
        k2s *= (1.0f / 16.0f);
        float L1 = 0.3f * (ce_s + k2s + ce_i);
        float L2 = 0.2f * (k1s + k2s);
        out[0] = 0.5f * (L1 + L2);
    }
}

// ---------------------------------------------------------------------------
extern "C" void kernel_launch(void* const* d_in, const int* in_sizes, int n_in,
                              void* d_out, int out_size) {
    const float* qh = (const float*)d_in[0];
    const float* ph = (const float*)d_in[1];
    if (n_in >= 2 && in_sizes[0] > in_sizes[1]) {
        const float* t = qh; qh = ph; ph = t;
    }

    cudaFuncSetAttribute(mv_tc_kernel, cudaFuncAttributeMaxDynamicSharedMemorySize,
                         DYN_SMEM);

    scores_kernel<<<PB, 512>>>(qh, ph);
    norm_warp_kernel<<<(QN * IN + PB * JN) / 8, 256>>>(qh, ph);
    mv_tc_kernel<<<dim3(PB, QN), 256, DYN_SMEM>>>();
    loss_kernel<<<1, 512>>>((float*)d_out);
}

// round 12
// speedup vs baseline: 1.2399x; 1.0776x over previous
#include <cuda_runtime.h>
#include <cuda_bf16.h>
#include <cstdint>
#include <math.h>

#define QN 16
#define IN 64
#define PB 128
#define JN 256
#define DN 768

#define NSLAB 12               // 768 / 64 bf16 per slab
#define A_STAGE 8192           // 64 rows x 128B
#define B_STAGE 32768          // 256 rows x 128B
#define STAGE_BYTES (A_STAGE + B_STAGE)   // 40960
#define DYN_SMEM (2 * STAGE_BYTES)        // 81920

// Scratch (device globals: no allocation)
__device__ __nv_bfloat16 g_qbf[QN * IN * DN];    // 1.5 MB normalized q, bf16
__device__ __nv_bfloat16 g_pbf[PB * JN * DN];    // 48 MB normalized p, bf16
__device__ float g_scores[QN * PB];
__device__ float g_mv[QN * PB];

// ---------------------------------------------------------------------------
// Helpers
// ---------------------------------------------------------------------------
static __device__ __forceinline__ uint32_t smem_u32(const void* p) {
    uint32_t a;
    asm("{ .reg .u64 t; cvta.to.shared.u64 t, %1; cvt.u32.u64 %0, t; }"
        : "=r"(a) : "l"(p));
    return a;
}

#define SWZ(o) ((o) ^ (((o) >> 3) & 0x70))

static __device__ __forceinline__ void cpasync16(uint32_t saddr, const void* g) {
    asm volatile("cp.async.cg.shared.global [%0], [%1], 16;" :: "r"(saddr), "l"(g) : "memory");
}

static __device__ __forceinline__ void mbar_init(uint32_t a, uint32_t cnt) {
    asm volatile("mbarrier.init.shared.b64 [%0], %1;" :: "r"(a), "r"(cnt) : "memory");
}

static __device__ __forceinline__ void mbar_wait(uint32_t a, uint32_t ph) {
    asm volatile(
        "{\n\t.reg .pred P;\n\t"
        "WL%=:\n\t"
        "mbarrier.try_wait.parity.shared.b64 P, [%0], %1;\n\t"
        "@!P bra WL%=;\n\t}"
        :: "r"(a), "r"(ph) : "memory");
}

static __device__ __forceinline__ void mbar_arrive(uint32_t a) {
    asm volatile("mbarrier.arrive.shared.b64 _, [%0];" :: "r"(a) : "memory");
}

// NOINC: one real arrival (counted in init count) when this thread's prior
// cp.asyncs complete. (Non-noinc form is self-balancing -> R9 hang.)
static __device__ __forceinline__ void cpasync_mbar_arrive_noinc(uint32_t a) {
    asm volatile("cp.async.mbarrier.arrive.noinc.shared.b64 [%0];" :: "r"(a) : "memory");
}

static __device__ __forceinline__ void ldmx4(uint32_t* r, uint32_t addr) {
    asm volatile("ldmatrix.sync.aligned.m8n8.x4.shared.b16 {%0,%1,%2,%3}, [%4];"
                 : "=r"(r[0]), "=r"(r[1]), "=r"(r[2]), "=r"(r[3]) : "r"(addr));
}

static __device__ __forceinline__ void mma_bf16(float* c, const uint32_t* a,
                                                uint32_t b0, uint32_t b1) {
    asm volatile(
        "mma.sync.aligned.m16n8k16.row.col.f32.bf16.bf16.f32 "
        "{%0,%1,%2,%3}, {%4,%5,%6,%7}, {%8,%9}, {%0,%1,%2,%3};"
        : "+f"(c[0]), "+f"(c[1]), "+f"(c[2]), "+f"(c[3])
        : "r"(a[0]), "r"(a[1]), "r"(a[2]), "r"(a[3]), "r"(b0), "r"(b1));
}

// ---------------------------------------------------------------------------
// prep kernel: blocks [0, PB) compute fp32 scores (8 warps x 2 q-dots each);
// blocks [PB, PB + 4224) normalize+convert rows, WARP per row (no smem/sync).
// Scores blocks lead the grid so they interleave with light norm blocks.
// ---------------------------------------------------------------------------
__global__ __launch_bounds__(256) void prep_kernel(const float* __restrict__ qh,
                                                   const float* __restrict__ ph) {
    const int w = threadIdx.x >> 5;
    const int lane = threadIdx.x & 31;

    if (blockIdx.x < PB) {
        // ---- scores for page p ----
        const int p = blockIdx.x;
        const float* pr = ph + (size_t)p * JN * DN;
#pragma unroll
        for (int half = 0; half < 2; half++) {
            const int q = w + 8 * half;
            const float* qr = qh + (size_t)q * IN * DN;
            float s = 0.f;
#pragma unroll
            for (int i = 0; i < DN / 32; i++)
                s = fmaf(qr[lane + 32 * i], pr[lane + 32 * i], s);
#pragma unroll
            for (int o = 16; o; o >>= 1) s += __shfl_xor_sync(0xffffffffu, s, o);
            if (lane == 0) g_scores[q * PB + p] = s;
        }
        return;
    }

    // ---- norm: one warp per row ----
    const size_t row = (size_t)(blockIdx.x - PB) * 8 + w;
    const float* xr;
    __nv_bfloat162* yr;
    if (row < (size_t)(QN * IN)) {
        xr = qh + row * DN;
        yr = (__nv_bfloat162*)(g_qbf + row * DN);
    } else {
        size_t r = row - QN * IN;
        xr = ph + r * DN;
        yr = (__nv_bfloat162*)(g_pbf + r * DN);
    }

    float4 v[6];
    float ss = 0.f;
#pragma unroll
    for (int c = 0; c < 6; c++) {
        v[c] = ((const float4*)xr)[lane + 32 * c];
        ss += v[c].x * v[c].x + v[c].y * v[c].y + v[c].z * v[c].z + v[c].w * v[c].w;
    }
#pragma unroll
    for (int o = 16; o; o >>= 1) ss += __shfl_xor_sync(0xffffffffu, ss, o);
    const float inv = 1.0f / fmaxf(sqrtf(ss), 1e-12f);

#pragma unroll
    for (int c = 0; c < 6; c++) {
        int idx = lane + 32 * c;
        yr[2 * idx + 0] = __floats2bfloat162_rn(v[c].x * inv, v[c].y * inv);
        yr[2 * idx + 1] = __floats2bfloat162_rn(v[c].z * inv, v[c].w * inv);
    }
}

// ---------------------------------------------------------------------------
// mv GEMM via bf16 mma.sync m16n8k16 on pre-normalized bf16 data.
// Grid (p=128, q=16). CTA tile 64(i) x 256(j), K=768 in 12 slabs of 64.
// 8 warps = 2(m) x 4(n); warp tile 32x64 = 2(mt) x 8(nt) fragments.
// 2-stage mbarrier ring, mainloop unrolled in buf0/buf1 pairs (static
// barrier selects, no per-slab branches). 2 CTAs/SM.
// ---------------------------------------------------------------------------
static __device__ __forceinline__ void load_slab(uint32_t stage_base, int mb, int p,
                                                 int k0, int tid) {
    // A: 64 rows x 64 bf16 (128B) = 512 x 16B chunks, 2 per thread
#pragma unroll
    for (int i = 0; i < 2; i++) {
        int idx = tid + 256 * i;
        int r = idx >> 3, c = idx & 7;
        const __nv_bfloat16* g = g_qbf + (size_t)(mb * 64 + r) * DN + k0 + c * 8;
        cpasync16(stage_base + SWZ(r * 128 + c * 16), g);
    }
    // B: 256 rows x 64 bf16 = 2048 x 16B, 8 per thread
    uint32_t bbase = stage_base + A_STAGE;
#pragma unroll
    for (int i = 0; i < 8; i++) {
        int idx = tid + 256 * i;
        int r = idx >> 3, c = idx & 7;
        const __nv_bfloat16* g = g_pbf + (size_t)(p * 256 + r) * DN + k0 + c * 8;
        cpasync16(bbase + SWZ(r * 128 + c * 16), g);
    }
}

struct MvCtx {
    uint32_t aRowOff[2];
    uint32_t bRowOff0;
    int achunk_h, bchunk_h, arx, brx;
};

static __device__ __forceinline__ void compute_slab(const MvCtx& cx, uint32_t Ab,
                                                    float acc[2][8][4]) {
    const uint32_t Bb = Ab + A_STAGE;
#pragma unroll
    for (int kk = 0; kk < 4; kk++) {
        const int ca = ((kk * 2 + cx.achunk_h) ^ cx.arx) << 4;
        const int cb = ((kk * 2 + cx.bchunk_h) ^ cx.brx) << 4;
        uint32_t a[2][4];
        ldmx4(a[0], Ab + cx.aRowOff[0] + ca);
        ldmx4(a[1], Ab + cx.aRowOff[1] + ca);
#pragma unroll
        for (int np = 0; np < 4; np++) {
            uint32_t b[4];
            ldmx4(b, Bb + cx.bRowOff0 + (uint32_t)np * 2048u + cb);
            mma_bf16(acc[0][np * 2 + 0], a[0], b[0], b[1]);
            mma_bf16(acc[1][np * 2 + 0], a[1], b[0], b[1]);
            mma_bf16(acc[0][np * 2 + 1], a[0], b[2], b[3]);
            mma_bf16(acc[1][np * 2 + 1], a[1], b[2], b[3]);
        }
    }
}

__global__ __launch_bounds__(256, 2) void mv_tc_kernel() {
    extern __shared__ __align__(128) char dynraw[];
    __shared__ __align__(8) unsigned long long s_full[2], s_empty[2];
    __shared__ float s_wmax[8];

    const int tid = threadIdx.x;
    const int p = blockIdx.x;
    const int mb = blockIdx.y;
    const int w = tid >> 5, lane = tid & 31;
    const int wm = w >> 2, wn = w & 3;

    const uint32_t dynbase = smem_u32(dynraw);
    const uint32_t full0 = smem_u32(&s_full[0]), full1 = smem_u32(&s_full[1]);
    const uint32_t empty0 = smem_u32(&s_empty[0]), empty1 = smem_u32(&s_empty[1]);

    if (tid == 0) {
        mbar_init(full0, 256); mbar_init(full1, 256);
        mbar_init(empty0, 8);  mbar_init(empty1, 8);
    }
    __syncthreads();

    MvCtx cx;
    {
        const int selA = lane >> 3;
        const int arow_l = (lane & 7) + ((selA & 1) << 3);
        cx.achunk_h = selA >> 1;
        cx.arx = lane & 7;
#pragma unroll
        for (int mt = 0; mt < 2; mt++)
            cx.aRowOff[mt] = (uint32_t)(wm * 32 + mt * 16 + arow_l) * 128u;
        const int jrow_l = (lane & 7) + ((lane >> 4) << 3);
        cx.bchunk_h = (lane >> 3) & 1;
        cx.brx = lane & 7;
        cx.bRowOff0 = (uint32_t)(wn * 64 + jrow_l) * 128u;
    }

    float acc[2][8][4];
#pragma unroll
    for (int mt = 0; mt < 2; mt++)
#pragma unroll
        for (int nt = 0; nt < 8; nt++)
#pragma unroll
            for (int c = 0; c < 4; c++) acc[mt][nt][c] = 0.f;

    // Prologue: fill both stages
    load_slab(dynbase, mb, p, 0, tid);
    cpasync_mbar_arrive_noinc(full0);
    load_slab(dynbase + STAGE_BYTES, mb, p, 64, tid);
    cpasync_mbar_arrive_noinc(full1);

    int phF0 = 0, phF1 = 0, phE0 = 0, phE1 = 0;

    // Mainloop: 6 iterations x 2 slabs (buf0, buf1), statically selected
#pragma unroll 1
    for (int it = 0; it < NSLAB / 2; it++) {
        const int s0 = 2 * it;
        // -- slab s0 on buf0 --
        mbar_wait(full0, (uint32_t)phF0); phF0 ^= 1;
        compute_slab(cx, dynbase, acc);
        if (lane == 0) mbar_arrive(empty0);
        if (s0 + 2 < NSLAB) {
            mbar_wait(empty0, (uint32_t)phE0); phE0 ^= 1;
            load_slab(dynbase, mb, p, (s0 + 2) * 64, tid);
            cpasync_mbar_arrive_noinc(full0);
        }
        // -- slab s0+1 on buf1 --
        mbar_wait(full1, (uint32_t)phF1); phF1 ^= 1;
        compute_slab(cx, dynbase + STAGE_BYTES, acc);
        if (lane == 0) mbar_arrive(empty1);
        if (s0 + 3 < NSLAB) {
            mbar_wait(empty1, (uint32_t)phE1); phE1 ^= 1;
            load_slab(dynbase + STAGE_BYTES, mb, p, (s0 + 3) * 64, tid);
            cpasync_mbar_arrive_noinc(full1);
        }
    }

    // Epilogue: pure max (operands pre-normalized)
    float mx = -INFINITY;
#pragma unroll
    for (int mt = 0; mt < 2; mt++)
#pragma unroll
        for (int nt = 0; nt < 8; nt++)
#pragma unroll
            for (int c = 0; c < 4; c++) mx = fmaxf(mx, acc[mt][nt][c]);
#pragma unroll
    for (int o = 16; o; o >>= 1) mx = fmaxf(mx, __shfl_xor_sync(0xffffffffu, mx, o));
    if (lane == 0) s_wmax[w] = mx;
    __syncthreads();
    if (tid == 0) {
        float m = s_wmax[0];
#pragma unroll
        for (int i = 1; i < 8; i++) m = fmaxf(m, s_wmax[i]);
        g_mv[mb * PB + p] = m;
    }
}

// ---------------------------------------------------------------------------
// Final loss (unchanged logic)
// ---------------------------------------------------------------------------
__global__ void loss_kernel(float* __restrict__ out) {
    int tid = threadIdx.x;  // 512
    int w = tid >> 5;
    int lane = tid & 31;
    const float* sr = g_scores + w * PB;
    const float* mr = g_mv + w * PB;
    float s[4], m[4], si[4];
#pragma unroll
    for (int c = 0; c < 4; c++) {
        int j = lane + 32 * c;
        s[c] = sr[j];
        m[c] = mr[j];
        si[c] = s[c] + 0.3f * m[c];
    }
    float mxs = -INFINITY, mxm = -INFINITY, mxi = -INFINITY;
#pragma unroll
    for (int c = 0; c < 4; c++) {
        mxs = fmaxf(mxs, s[c]);
        mxm = fmaxf(mxm, m[c]);
        mxi = fmaxf(mxi, si[c]);
    }
#pragma unroll
    for (int o = 16; o; o >>= 1) {
        mxs = fmaxf(mxs, __shfl_xor_sync(0xffffffffu, mxs, o));
        mxm = fmaxf(mxm, __shfl_xor_sync(0xffffffffu, mxm, o));
        mxi = fmaxf(mxi, __shfl_xor_sync(0xffffffffu, mxi, o));
    }
    float es = 0.f, em = 0.f, ei = 0.f;
#pragma unroll
    for (int c = 0; c < 4; c++) {
        es += expf(s[c] - mxs);
        em += expf(m[c] - mxm);
        ei += expf(si[c] - mxi);
    }
#pragma unroll
    for (int o = 16; o; o >>= 1) {
        es += __shfl_xor_sync(0xffffffffu, es, o);
        em += __shfl_xor_sync(0xffffffffu, em, o);
        ei += __shfl_xor_sync(0xffffffffu, ei, o);
    }
    float lse_s = mxs + logf(es);
    float lse_m = mxm + logf(em);
    float lse_i = mxi + logf(ei);

    float k1 = 0.f, k2 = 0.f;
#pragma unroll
    for (int c = 0; c < 4; c++) {
        float t = si[c] - lse_i;
        float pb = expf(t);
        k1 += pb * (t - (s[c] - lse_s));
        k2 += pb * (t - (m[c] - lse_m));
    }
#pragma unroll
    for (int o = 16; o; o >>= 1) {
        k1 += __shfl_xor_sync(0xffffffffu, k1, o);
        k2 += __shfl_xor_sync(0xffffffffu, k2, o);
    }

    __shared__ float sm[16][4];
    if (lane == 0) {
        int tgt = w * 8;
        sm[w][0] = lse_s - sr[tgt];
        sm[w][1] = lse_i - (sr[tgt] + 0.3f * mr[tgt]);
        sm[w][2] = k1;
        sm[w][3] = k2;
    }
    __syncthreads();
    if (tid == 0) {
        float ce_s = 0.f, ce_i = 0.f, k1s = 0.f, k2s = 0.f;
#pragma unroll
        for (int i = 0; i < 16; i++) {
            ce_s += sm[i][0];
            ce_i += sm[i][1];
            k1s += sm[i][2];
            k2s += sm[i][3];
        }
        ce_s *= (1.0f / 16.0f);
        ce_i *= (1.0f / 16.0f);
        k1s *= (1.0f / 16.0f);
        k2s *= (1.0f / 16.0f);
        float L1 = 0.3f * (ce_s + k2s + ce_i);
        float L2 = 0.2f * (k1s + k2s);
        out[0] = 0.5f * (L1 + L2);
    }
}

// ---------------------------------------------------------------------------
extern "C" void kernel_launch(void* const* d_in, const int* in_sizes, int n_in,
                              void* d_out, int out_size) {
    const float* qh = (const float*)d_in[0];
    const float* ph = (const float*)d_in[1];
    if (n_in >= 2 && in_sizes[0] > in_sizes[1]) {
        const float* t = qh; qh = ph; ph = t;
    }

    cudaFuncSetAttribute(mv_tc_kernel, cudaFuncAttributeMaxDynamicSharedMemorySize,
                         DYN_SMEM);

    prep_kernel<<<PB + (QN * IN + PB * JN) / 8, 256>>>(qh, ph);
    mv_tc_kernel<<<dim3(PB, QN), 256, DYN_SMEM>>>();
    loss_kernel<<<1, 512>>>((float*)d_out);
}